// round 1
// baseline (speedup 1.0000x reference)
#include <cuda_runtime.h>

// Detail_loss: loss = mean|conv(x,kh)-conv(y,kh)|/2 + mean|conv(x,kv)-conv(y,kv)|/2
// with fixed [-0.5,0,0.5] gradient kernels broadcast over 3x3 channel pairs.
// Reduces to: S = sum_c(infer-ref); accumulate |S[h,w+1]-S[h,w-1]| + |S[h+1,w]-S[h-1,w]|
// over all pixels (zero padding), scaled by 1/(4 * N * 258 * 256).

#define H 256
#define W 256
#define C 3
#define RSTRIP 32              // image rows processed per block
#define SHROWS (RSTRIP + 2)    // +1 halo row top/bottom
#define STRIPS (H / RSTRIP)    // 8

__device__ double g_acc;

__global__ void dl_init() { g_acc = 0.0; }

__global__ __launch_bounds__(256)
void dl_main(const float* __restrict__ infer, const float* __restrict__ ref) {
    __shared__ float S[SHROWS][W];
    __shared__ float wsum[8];

    const int b    = blockIdx.x;
    const int n    = b >> 3;           // image index
    const int s    = b & 7;            // strip index
    const int row0 = s * RSTRIP - 1;   // global image row of shared row 0
    const size_t base = (size_t)n * (C * H * W);
    const int tid = threadIdx.x;

    // ---- Load phase: build channel-summed diff tile S (with zero halo) ----
    // SHROWS * (W/4) = 34*64 = 2176 float4 tasks over 256 threads.
    for (int idx = tid; idx < SHROWS * (W / 4); idx += 256) {
        const int r  = idx >> 6;            // shared row
        const int c4 = (idx & 63) << 2;     // starting column (float4)
        const int g  = row0 + r;            // global image row
        float4 v = make_float4(0.f, 0.f, 0.f, 0.f);
        if ((unsigned)g < (unsigned)H) {
            const size_t off = base + (size_t)g * W + c4;
            #pragma unroll
            for (int ch = 0; ch < C; ch++) {
                const float4 a  = __ldg((const float4*)(infer + off + (size_t)ch * (H * W)));
                const float4 bb = __ldg((const float4*)(ref   + off + (size_t)ch * (H * W)));
                v.x += a.x - bb.x;
                v.y += a.y - bb.y;
                v.z += a.z - bb.z;
                v.w += a.w - bb.w;
            }
        }
        *(float4*)&S[r][c4] = v;
    }
    __syncthreads();

    // ---- Compute phase: one thread per column, 32 rows each ----
    const int c = tid;
    float acc = 0.f;
    #pragma unroll 4
    for (int rr = 1; rr <= RSTRIP; rr++) {
        const float sl = (c > 0)     ? S[rr][c - 1] : 0.f;
        const float sr = (c < W - 1) ? S[rr][c + 1] : 0.f;
        acc += fabsf(sr - sl);                       // 2*|G_h|
        acc += fabsf(S[rr + 1][c] - S[rr - 1][c]);   // 2*|G_v|
    }

    // ---- Block reduction ----
    #pragma unroll
    for (int o = 16; o; o >>= 1) acc += __shfl_down_sync(0xffffffffu, acc, o);
    if ((tid & 31) == 0) wsum[tid >> 5] = acc;
    __syncthreads();
    if (tid == 0) {
        float t = 0.f;
        #pragma unroll
        for (int i = 0; i < 8; i++) t += wsum[i];
        atomicAdd(&g_acc, (double)t);
    }
}

__global__ void dl_final(float* out, int n_img) {
    // accumulated 2*|G| terms -> multiply by 0.5; loss = (Sh+Sv)/(2*N*258*256)
    out[0] = (float)(g_acc / (4.0 * (double)n_img * 258.0 * 256.0));
}

extern "C" void kernel_launch(void* const* d_in, const int* in_sizes, int n_in,
                              void* d_out, int out_size) {
    const float* infer = (const float*)d_in[0];
    const float* ref   = (const float*)d_in[1];
    const int n_img = in_sizes[0] / (C * H * W);   // 2*7*7 = 98

    dl_init<<<1, 1>>>();
    dl_main<<<n_img * STRIPS, 256>>>(infer, ref);
    dl_final<<<1, 1>>>((float*)d_out, n_img);
}